// round 4
// baseline (speedup 1.0000x reference)
#include <cuda_runtime.h>

// ---------------------------------------------------------------------------
// Problem constants (from reference setup_inputs; steps fixed at 30)
// ---------------------------------------------------------------------------
#define IN_DIM   1024
#define HID      2048
#define OUT_DIM  1000
#define BATCH    4096
#define STEPS    30
#define NPI      30         // power iterations
#define EPSN     1e-12f

// Power-iteration block groups (blocks per matrix)
// Divisibility: cpb=N/G; tpc=256/cpb must divide M (in/rec M=2048 pow2; out M=1000 -> tpc=8)
#define G_IN  128   // cpb=8,  tpc=32, rps=64
#define G_REC 256   // cpb=8,  tpc=32, rps=64
#define G_OUT 64    // cpb=32, tpc=8,  rps=125
#define NB_PI (G_IN + G_REC + G_OUT)   // 448 blocks

// ---------------------------------------------------------------------------
// Device scratch (allocation-free rule: __device__ globals)
// ---------------------------------------------------------------------------
__device__ float g_u[6144];        // raw u: in@0 (2048), rec@2048 (2048), out@4096 (1000)
__device__ float g_y[6144];        // raw y: in@0 (1024), rec@2048 (2048), out@4096 (2048)
__device__ float g_partY[3][256];  // per-block sumsq partials, phase Y
__device__ float g_partZ[3][256];  // per-block sumsq partials, phase Z
__device__ float g_sigpart[3][256];// sigma partials
__device__ float g_inv_sigma[3];

__device__ float g_xproj[(size_t)BATCH * HID];
__device__ float g_h0[(size_t)BATCH * HID];
__device__ float g_h1[(size_t)BATCH * HID];

// ---------------------------------------------------------------------------
// Power iteration: W is [M, N] row-major (out x in).
// Reference per iter: v = norm(W^T u); u = norm(W v).
// Kernel boundaries act as grid barriers. Each block writes its own partial
// slot (plain store, no atomics -> deterministic, no reset needed).
// ---------------------------------------------------------------------------
struct PiCtx {
    int m, bg, G, M, N;
    const float* W;
    float* ubuf;
    float* ybuf;
};

__device__ __forceinline__ PiCtx pi_ctx(int b, const float* Win, const float* Wrec,
                                        const float* Wout) {
    PiCtx c;
    if (b < G_IN) {
        c.m = 0; c.bg = b;               c.G = G_IN;  c.M = HID;     c.N = IN_DIM;
        c.W = Win;  c.ubuf = g_u;        c.ybuf = g_y;
    } else if (b < G_IN + G_REC) {
        c.m = 1; c.bg = b - G_IN;        c.G = G_REC; c.M = HID;     c.N = HID;
        c.W = Wrec; c.ubuf = g_u + 2048; c.ybuf = g_y + 2048;
    } else {
        c.m = 2; c.bg = b - G_IN - G_REC; c.G = G_OUT; c.M = OUT_DIM; c.N = HID;
        c.W = Wout; c.ubuf = g_u + 4096;  c.ybuf = g_y + 4096;
    }
    return c;
}

// Init: u = ones (raw), partZ set so that su = 1/(sqrt(M)+eps) on first phaseY.
__global__ void pi_init() {
    int t = threadIdx.x;
    for (int i = t; i < 2048; i += 256) {
        g_u[i] = 1.0f;
        g_u[2048 + i] = 1.0f;
        if (i < OUT_DIM) g_u[4096 + i] = 1.0f;
    }
    for (int g = t; g < 256; g += 256) {
        g_partZ[0][g] = 0.0f; g_partZ[1][g] = 0.0f; g_partZ[2][g] = 0.0f;
    }
    if (t == 0) {
        g_partZ[0][0] = (float)HID;
        g_partZ[1][0] = (float)HID;
        g_partZ[2][0] = (float)OUT_DIM;
    }
}

// Phase Y: ybuf = W^T u_hat  (u_hat = su * ubuf, su derived from partZ).
__global__ void pi_phaseY(const float* __restrict__ Win, const float* __restrict__ Wrec,
                          const float* __restrict__ Wout) {
    PiCtx c = pi_ctx(blockIdx.x, Win, Wrec, Wout);
    float ss = 0.0f;
    for (int g = 0; g < c.G; ++g) ss += g_partZ[c.m][g];     // fixed order: deterministic
    float su = 1.0f / (sqrtf(ss) + EPSN);

    int cpb = c.N / c.G;          // cols per block
    int tpc = 256 / cpb;          // threads per col
    int cl  = threadIdx.x % cpb;
    int seg = threadIdx.x / cpb;
    int col = c.bg * cpb + cl;
    int rps = c.M / tpc;          // rows per segment (exact by construction)
    int r0  = seg * rps;

    float acc = 0.0f;
    const float* Wc = c.W + col;
    for (int i = r0; i < r0 + rps; ++i)
        acc += Wc[(size_t)i * c.N] * c.ubuf[i];

    __shared__ float red[256];
    __shared__ float ssq[64];
    red[threadIdx.x] = acc;
    __syncthreads();
    if (seg == 0) {
        float tot = 0.0f;
        for (int s = 0; s < tpc; ++s) tot += red[cl + s * cpb];
        float yv = tot * su;
        c.ybuf[col] = yv;
        ssq[cl] = yv * yv;
    }
    __syncthreads();
    if (threadIdx.x == 0) {
        float p = 0.0f;
        for (int q = 0; q < cpb; ++q) p += ssq[q];
        g_partY[c.m][c.bg] = p;
    }
}

// Phase Z: ubuf = W v_hat  (v_hat = sv * ybuf). Warp per row, shfl reduce.
__global__ void pi_phaseZ(const float* __restrict__ Win, const float* __restrict__ Wrec,
                          const float* __restrict__ Wout) {
    PiCtx c = pi_ctx(blockIdx.x, Win, Wrec, Wout);
    float ss = 0.0f;
    for (int g = 0; g < c.G; ++g) ss += g_partY[c.m][g];
    float sv = 1.0f / (sqrtf(ss) + EPSN);

    int warp = threadIdx.x >> 5, lane = threadIdx.x & 31;
    int rpb = (c.M + c.G - 1) / c.G;
    int rend = min(c.bg * rpb + rpb, c.M);

    float acc2 = 0.0f;
    for (int r = c.bg * rpb + warp; r < rend; r += 8) {
        const float* row = c.W + (size_t)r * c.N;
        float a = 0.0f;
        for (int j = lane; j < c.N; j += 32) a += row[j] * c.ybuf[j];
        for (int o = 16; o; o >>= 1) a += __shfl_down_sync(0xffffffffu, a, o);
        if (lane == 0) {
            float z = a * sv;
            c.ubuf[r] = z;
            acc2 += z * z;
        }
    }
    __shared__ float wsq[8];
    if (lane == 0) wsq[warp] = acc2;
    __syncthreads();
    if (threadIdx.x == 0) {
        float p = 0.0f;
        for (int w = 0; w < 8; ++w) p += wsq[w];
        g_partZ[c.m][c.bg] = p;
    }
}

// sigma = u_hat . (W v_hat); u_hat = su*ubuf (partZ), v_hat = sv*ybuf (partY).
__global__ void pi_sigma(const float* __restrict__ Win, const float* __restrict__ Wrec,
                         const float* __restrict__ Wout) {
    PiCtx c = pi_ctx(blockIdx.x, Win, Wrec, Wout);
    float ssz = 0.0f, ssy = 0.0f;
    for (int g = 0; g < c.G; ++g) { ssz += g_partZ[c.m][g]; ssy += g_partY[c.m][g]; }
    float su = 1.0f / (sqrtf(ssz) + EPSN);
    float sv = 1.0f / (sqrtf(ssy) + EPSN);

    int warp = threadIdx.x >> 5, lane = threadIdx.x & 31;
    int rpb = (c.M + c.G - 1) / c.G;
    int rend = min(c.bg * rpb + rpb, c.M);

    float contrib = 0.0f;
    for (int r = c.bg * rpb + warp; r < rend; r += 8) {
        const float* row = c.W + (size_t)r * c.N;
        float a = 0.0f;
        for (int j = lane; j < c.N; j += 32) a += row[j] * c.ybuf[j];
        for (int o = 16; o; o >>= 1) a += __shfl_down_sync(0xffffffffu, a, o);
        if (lane == 0) contrib += (su * c.ubuf[r]) * (sv * a);
    }
    __shared__ float wsq[8];
    if (lane == 0) wsq[warp] = contrib;
    __syncthreads();
    if (threadIdx.x == 0) {
        float p = 0.0f;
        for (int w = 0; w < 8; ++w) p += wsq[w];
        g_sigpart[c.m][c.bg] = p;
    }
}

__global__ void pi_finalize() {
    int m = threadIdx.x;
    if (m < 3) {
        int G = (m == 1) ? G_REC : ((m == 0) ? G_IN : G_OUT);
        float s = 0.0f;
        for (int g = 0; g < G; ++g) s += g_sigpart[m][g];
        g_inv_sigma[m] = 1.0f / s;
    }
}

// ---------------------------------------------------------------------------
// 3xTF32 tensor-core GEMM (NT):
//   C[m,n] = epi( (sum_k A[m,k]*B[n,k]) * inv_sigma + bias[n] [+ add] [tanh] )
// A: [M,K] row-major. B: [N,K] row-major.
// Each fp32 x is split once (at smem fill) into hi = tf32(x), lo = tf32(x-hi);
// A.B accumulated as Ahi.Bhi + Ahi.Blo + Alo.Bhi  (error ~2^-24: fp32-grade).
// Tile 128x128x16, 8 warps each 64(M)x32(N), mma.sync.m16n8k8.tf32.
// ---------------------------------------------------------------------------
#define BM 128
#define BN 128
#define BKT 16
#define SKS 20   // smem row stride in float2 (=> 160B rows: conflict-free lds.64 frags)

__device__ __forceinline__ float2 split_tf32(float x) {
    unsigned hu, lu;
    asm("cvt.rna.tf32.f32 %0, %1;" : "=r"(hu) : "f"(x));
    float hi = __uint_as_float(hu);
    float r = x - hi;
    asm("cvt.rna.tf32.f32 %0, %1;" : "=r"(lu) : "f"(r));
    return make_float2(hi, __uint_as_float(lu));
}

__device__ __forceinline__ void mma8(float* c, unsigned a0, unsigned a1, unsigned a2,
                                     unsigned a3, unsigned b0, unsigned b1) {
    asm volatile(
        "mma.sync.aligned.m16n8k8.row.col.f32.tf32.tf32.f32 "
        "{%0,%1,%2,%3}, {%4,%5,%6,%7}, {%8,%9}, {%0,%1,%2,%3};"
        : "+f"(c[0]), "+f"(c[1]), "+f"(c[2]), "+f"(c[3])
        : "r"(a0), "r"(a1), "r"(a2), "r"(a3), "r"(b0), "r"(b1));
}

template <bool DO_TANH, bool HAS_ADD>
__global__ __launch_bounds__(256)
void gemm_tf32(const float* __restrict__ A, const float* __restrict__ B,
               const float* __restrict__ bias, const float* __restrict__ add,
               float* __restrict__ C, int M, int N, int K, int sidx) {
    __shared__ float2 As[BM * SKS];   // [row][k] {hi,lo}, 20 KB
    __shared__ float2 Bs[BN * SKS];   // 20 KB

    int tid = threadIdx.x;
    int bm = blockIdx.y * BM, bn = blockIdx.x * BN;

    // global-load mapping: row = tid/2, 8 consecutive k per thread
    int lrow = tid >> 1;
    int lseg = (tid & 1) * 8;
    const float* Aptr = A + (size_t)(bm + lrow) * K + lseg;
    bool brow_ok = (bn + lrow) < N;
    const float* Bptr = B + (size_t)(bn + lrow) * K + lseg;

    // warp tiling: 2(M) x 4(N) warps; warp tile 64x32
    int warp = tid >> 5, lane = tid & 31;
    int wm = (warp & 1) * 64;
    int wn = (warp >> 1) * 32;
    int g = lane >> 2;      // group id (0..7)
    int t = lane & 3;       // thread-in-group (0..3)

    float acc[4][4][4];     // [mf][nf][c0..c3]
#pragma unroll
    for (int i = 0; i < 4; ++i)
#pragma unroll
        for (int j = 0; j < 4; ++j)
#pragma unroll
            for (int q = 0; q < 4; ++q) acc[i][j][q] = 0.0f;

    // prefetch tile 0
    float4 a0v = *(const float4*)(Aptr);
    float4 a1v = *(const float4*)(Aptr + 4);
    float4 b0v = make_float4(0.f, 0.f, 0.f, 0.f), b1v = b0v;
    if (brow_ok) { b0v = *(const float4*)(Bptr); b1v = *(const float4*)(Bptr + 4); }

    int KT = K / BKT;
    for (int kt = 0; kt < KT; ++kt) {
        __syncthreads();   // previous tile fully consumed
        {
            float af[8] = {a0v.x, a0v.y, a0v.z, a0v.w, a1v.x, a1v.y, a1v.z, a1v.w};
            float bf[8] = {b0v.x, b0v.y, b0v.z, b0v.w, b1v.x, b1v.y, b1v.z, b1v.w};
#pragma unroll
            for (int j = 0; j < 8; ++j) {
                As[lrow * SKS + lseg + j] = split_tf32(af[j]);
                Bs[lrow * SKS + lseg + j] = split_tf32(bf[j]);
            }
        }
        __syncthreads();

        // issue next tile's global loads; latency hidden under mma below
        if (kt + 1 < KT) {
            int off = (kt + 1) * BKT;
            a0v = *(const float4*)(Aptr + off);
            a1v = *(const float4*)(Aptr + off + 4);
            if (brow_ok) {
                b0v = *(const float4*)(Bptr + off);
                b1v = *(const float4*)(Bptr + off + 4);
            }
        }

#pragma unroll
        for (int kc = 0; kc < BKT; kc += 8) {
            // A fragments: 4 m-frags x {a0..a3}, hi+lo packed in float2
            float2 Af[4][4];
#pragma unroll
            for (int mf = 0; mf < 4; ++mf) {
                int rb = wm + mf * 16 + g;
                Af[mf][0] = As[rb * SKS + kc + t];
                Af[mf][1] = As[(rb + 8) * SKS + kc + t];
                Af[mf][2] = As[rb * SKS + kc + t + 4];
                Af[mf][3] = As[(rb + 8) * SKS + kc + t + 4];
            }
#pragma unroll
            for (int nf = 0; nf < 4; ++nf) {
                int cb = wn + nf * 8 + g;
                float2 Bf0 = Bs[cb * SKS + kc + t];
                float2 Bf1 = Bs[cb * SKS + kc + t + 4];
                unsigned bh0 = __float_as_uint(Bf0.x), bh1 = __float_as_uint(Bf1.x);
                unsigned bl0 = __float_as_uint(Bf0.y), bl1 = __float_as_uint(Bf1.y);
#pragma unroll
                for (int mf = 0; mf < 4; ++mf) {
                    unsigned ah0 = __float_as_uint(Af[mf][0].x), ah1 = __float_as_uint(Af[mf][1].x);
                    unsigned ah2 = __float_as_uint(Af[mf][2].x), ah3 = __float_as_uint(Af[mf][3].x);
                    unsigned al0 = __float_as_uint(Af[mf][0].y), al1 = __float_as_uint(Af[mf][1].y);
                    unsigned al2 = __float_as_uint(Af[mf][2].y), al3 = __float_as_uint(Af[mf][3].y);
                    mma8(acc[mf][nf], ah0, ah1, ah2, ah3, bh0, bh1);   // hi*hi
                    mma8(acc[mf][nf], ah0, ah1, ah2, ah3, bl0, bl1);   // hi*lo
                    mma8(acc[mf][nf], al0, al1, al2, al3, bh0, bh1);   // lo*hi
                }
            }
        }
    }

    // ---- epilogue ----
    float scale = g_inv_sigma[sidx];
    bool full = (bn + BN <= N);
#pragma unroll
    for (int mf = 0; mf < 4; ++mf) {
        int r0 = bm + wm + mf * 16 + g;
#pragma unroll
        for (int nf = 0; nf < 4; ++nf) {
            int c0 = bn + wn + nf * 8 + 2 * t;
            float* a = acc[mf][nf];
#pragma unroll
            for (int half = 0; half < 2; ++half) {
                int rr = r0 + half * 8;
                size_t base = (size_t)rr * N + c0;
                float v0 = a[half * 2 + 0];
                float v1 = a[half * 2 + 1];
                if (full) {
                    v0 = v0 * scale + bias[c0];
                    v1 = v1 * scale + bias[c0 + 1];
                    if (HAS_ADD) {
                        float2 ad = *(const float2*)(add + base);
                        v0 += ad.x; v1 += ad.y;
                    }
                    if (DO_TANH) { v0 = tanhf(v0); v1 = tanhf(v1); }
                    float2 o; o.x = v0; o.y = v1;
                    *(float2*)(C + base) = o;
                } else {
                    if (c0 < N) {
                        float w = v0 * scale + bias[c0];
                        if (HAS_ADD) w += add[base];
                        if (DO_TANH) w = tanhf(w);
                        C[base] = w;
                    }
                    if (c0 + 1 < N) {
                        float w = v1 * scale + bias[c0 + 1];
                        if (HAS_ADD) w += add[base + 1];
                        if (DO_TANH) w = tanhf(w);
                        C[base + 1] = w;
                    }
                }
            }
        }
    }
}

// Step 1 (h0 = 0): h = tanh(x_proj + b_rec), elementwise.
__global__ void step1_kernel(const float* __restrict__ xp, const float* __restrict__ brec,
                             float* __restrict__ h) {
    size_t i = ((size_t)blockIdx.x * blockDim.x + threadIdx.x) * 4;
    float4 v = *(const float4*)(xp + i);
    int col = (int)(i & (HID - 1));
    v.x = tanhf(v.x + brec[col + 0]);
    v.y = tanhf(v.y + brec[col + 1]);
    v.z = tanhf(v.z + brec[col + 2]);
    v.w = tanhf(v.w + brec[col + 3]);
    *(float4*)(h + i) = v;
}

// ---------------------------------------------------------------------------
// Launch
// ---------------------------------------------------------------------------
extern "C" void kernel_launch(void* const* d_in, const int* in_sizes, int n_in,
                              void* d_out, int out_size) {
    (void)in_sizes; (void)n_in; (void)out_size;
    const float* x    = (const float*)d_in[0];
    const float* Win  = (const float*)d_in[1];
    const float* bin  = (const float*)d_in[2];
    const float* Wrec = (const float*)d_in[3];
    const float* brec = (const float*)d_in[4];
    const float* Wout = (const float*)d_in[5];
    const float* bout = (const float*)d_in[6];
    float* out = (float*)d_out;

    float *xproj, *h0, *h1;
    cudaGetSymbolAddress((void**)&xproj, g_xproj);
    cudaGetSymbolAddress((void**)&h0, g_h0);
    cudaGetSymbolAddress((void**)&h1, g_h1);

    // --- spectral norms (power iteration, fp32, exact reference sequence) ---
    pi_init<<<1, 256>>>();
    for (int it = 0; it < NPI; ++it) {
        pi_phaseY<<<NB_PI, 256>>>(Win, Wrec, Wout);
        pi_phaseZ<<<NB_PI, 256>>>(Win, Wrec, Wout);
    }
    pi_phaseY<<<NB_PI, 256>>>(Win, Wrec, Wout);   // final v = norm(W^T u)
    pi_sigma<<<NB_PI, 256>>>(Win, Wrec, Wout);    // sigma = u . (W v)
    pi_finalize<<<1, 32>>>();

    // --- x_proj = x @ Win^T / s_in + b_in ---
    gemm_tf32<false, false><<<dim3(HID / BN, BATCH / BM), 256>>>(
        x, Win, bin, nullptr, xproj, BATCH, HID, IN_DIM, 0);

    // --- step 1: h = tanh(x_proj + b_rec) (h0 == 0) ---
    step1_kernel<<<(BATCH * HID) / (256 * 4), 256>>>(xproj, brec, h0);

    // --- steps 2..30: h = tanh(x_proj + h @ Wrec^T / s_rec + b_rec) ---
    float* hin = h0;
    float* hout = h1;
    for (int s = 1; s < STEPS; ++s) {
        gemm_tf32<true, true><<<dim3(HID / BN, BATCH / BM), 256>>>(
            hin, Wrec, brec, xproj, hout, BATCH, HID, HID, 1);
        float* t = hin; hin = hout; hout = t;
    }

    // --- out = h @ Wout^T / s_out + b_out ---
    gemm_tf32<false, false><<<dim3((OUT_DIM + BN - 1) / BN, BATCH / BM), 256>>>(
        hin, Wout, bout, nullptr, out, BATCH, OUT_DIM, HID, 2);
}

// round 6
// speedup vs baseline: 2.1472x; 2.1472x over previous
#include <cuda_runtime.h>
#include <cstdint>

// ---------------------------------------------------------------------------
// Problem constants
// ---------------------------------------------------------------------------
#define IN_DIM   1024
#define HID      2048
#define OUT_DIM  1000
#define BATCH    4096
#define STEPS    30
#define NPI      30
#define EPSN     1e-12f

#define G_IN  128
#define G_REC 256
#define G_OUT 64
#define NB_PI (G_IN + G_REC + G_OUT)

// ---------------------------------------------------------------------------
// Device scratch (allocation-free rule: __device__ globals)
// ---------------------------------------------------------------------------
__device__ float g_u[6144];
__device__ float g_y[6144];
__device__ float g_partY[3][256];
__device__ float g_partZ[3][256];
__device__ float g_sigpart[3][256];
__device__ float g_inv_sigma[3];

__device__ float g_xproj[(size_t)BATCH * HID];
__device__ float g_h0[(size_t)BATCH * HID];
__device__ float g_h1[(size_t)BATCH * HID];

// ---------------------------------------------------------------------------
// Power iteration (fp32, reference-exact sequence; 4-way MLP unroll)
// ---------------------------------------------------------------------------
struct PiCtx { int m, bg, G, M, N; const float* W; float* ubuf; float* ybuf; };

__device__ __forceinline__ PiCtx pi_ctx(int b, const float* Win, const float* Wrec,
                                        const float* Wout) {
    PiCtx c;
    if (b < G_IN) {
        c.m = 0; c.bg = b; c.G = G_IN; c.M = HID; c.N = IN_DIM;
        c.W = Win; c.ubuf = g_u; c.ybuf = g_y;
    } else if (b < G_IN + G_REC) {
        c.m = 1; c.bg = b - G_IN; c.G = G_REC; c.M = HID; c.N = HID;
        c.W = Wrec; c.ubuf = g_u + 2048; c.ybuf = g_y + 2048;
    } else {
        c.m = 2; c.bg = b - G_IN - G_REC; c.G = G_OUT; c.M = OUT_DIM; c.N = HID;
        c.W = Wout; c.ubuf = g_u + 4096; c.ybuf = g_y + 4096;
    }
    return c;
}

__global__ void pi_init() {
    int t = threadIdx.x;
    for (int i = t; i < 2048; i += 256) {
        g_u[i] = 1.0f;
        g_u[2048 + i] = 1.0f;
        if (i < OUT_DIM) g_u[4096 + i] = 1.0f;
    }
    for (int g = t; g < 256; g += 256) {
        g_partZ[0][g] = 0.0f; g_partZ[1][g] = 0.0f; g_partZ[2][g] = 0.0f;
    }
    if (t == 0) {
        g_partZ[0][0] = (float)HID;
        g_partZ[1][0] = (float)HID;
        g_partZ[2][0] = (float)OUT_DIM;
    }
}

__global__ void pi_phaseY(const float* __restrict__ Win, const float* __restrict__ Wrec,
                          const float* __restrict__ Wout) {
    PiCtx c = pi_ctx(blockIdx.x, Win, Wrec, Wout);
    float ss = 0.0f;
    for (int g = 0; g < c.G; ++g) ss += g_partZ[c.m][g];   // fixed order: deterministic
    float su = 1.0f / (sqrtf(ss) + EPSN);

    int cpb = c.N / c.G;
    int tpc = 256 / cpb;
    int cl = threadIdx.x % cpb;
    int seg = threadIdx.x / cpb;
    int col = c.bg * cpb + cl;
    int rps = c.M / tpc;
    int r0 = seg * rps;

    const float* Wc = c.W + col;
    float a0 = 0.f, a1 = 0.f, a2 = 0.f, a3 = 0.f;
    int i = r0;
    for (; i + 3 < r0 + rps; i += 4) {
        a0 += Wc[(size_t)(i + 0) * c.N] * c.ubuf[i + 0];
        a1 += Wc[(size_t)(i + 1) * c.N] * c.ubuf[i + 1];
        a2 += Wc[(size_t)(i + 2) * c.N] * c.ubuf[i + 2];
        a3 += Wc[(size_t)(i + 3) * c.N] * c.ubuf[i + 3];
    }
    for (; i < r0 + rps; ++i) a0 += Wc[(size_t)i * c.N] * c.ubuf[i];
    float acc = (a0 + a1) + (a2 + a3);

    __shared__ float red[256];
    __shared__ float ssq[64];
    red[threadIdx.x] = acc;
    __syncthreads();
    if (seg == 0) {
        float tot = 0.0f;
        for (int s = 0; s < tpc; ++s) tot += red[cl + s * cpb];
        float yv = tot * su;
        c.ybuf[col] = yv;
        ssq[cl] = yv * yv;
    }
    __syncthreads();
    if (threadIdx.x == 0) {
        float p = 0.0f;
        for (int q = 0; q < cpb; ++q) p += ssq[q];
        g_partY[c.m][c.bg] = p;
    }
}

__global__ void pi_phaseZ(const float* __restrict__ Win, const float* __restrict__ Wrec,
                          const float* __restrict__ Wout) {
    PiCtx c = pi_ctx(blockIdx.x, Win, Wrec, Wout);
    float ss = 0.0f;
    for (int g = 0; g < c.G; ++g) ss += g_partY[c.m][g];
    float sv = 1.0f / (sqrtf(ss) + EPSN);

    int warp = threadIdx.x >> 5, lane = threadIdx.x & 31;
    int rpb = (c.M + c.G - 1) / c.G;
    int rend = min(c.bg * rpb + rpb, c.M);

    float acc2 = 0.0f;
    for (int r = c.bg * rpb + warp; r < rend; r += 8) {
        const float* row = c.W + (size_t)r * c.N;
        float a0 = 0.f, a1 = 0.f, a2 = 0.f, a3 = 0.f;
        for (int j = lane; j < c.N; j += 128) {   // N in {1024,2048}: divisible by 128
            a0 += row[j] * c.ybuf[j];
            a1 += row[j + 32] * c.ybuf[j + 32];
            a2 += row[j + 64] * c.ybuf[j + 64];
            a3 += row[j + 96] * c.ybuf[j + 96];
        }
        float a = (a0 + a1) + (a2 + a3);
        for (int o = 16; o; o >>= 1) a += __shfl_down_sync(0xffffffffu, a, o);
        if (lane == 0) {
            float z = a * sv;
            c.ubuf[r] = z;
            acc2 += z * z;
        }
    }
    __shared__ float wsq[8];
    if (lane == 0) wsq[warp] = acc2;
    __syncthreads();
    if (threadIdx.x == 0) {
        float p = 0.0f;
        for (int w = 0; w < 8; ++w) p += wsq[w];
        g_partZ[c.m][c.bg] = p;
    }
}

__global__ void pi_sigma(const float* __restrict__ Win, const float* __restrict__ Wrec,
                         const float* __restrict__ Wout) {
    PiCtx c = pi_ctx(blockIdx.x, Win, Wrec, Wout);
    float ssz = 0.0f, ssy = 0.0f;
    for (int g = 0; g < c.G; ++g) { ssz += g_partZ[c.m][g]; ssy += g_partY[c.m][g]; }
    float su = 1.0f / (sqrtf(ssz) + EPSN);
    float sv = 1.0f / (sqrtf(ssy) + EPSN);

    int warp = threadIdx.x >> 5, lane = threadIdx.x & 31;
    int rpb = (c.M + c.G - 1) / c.G;
    int rend = min(c.bg * rpb + rpb, c.M);

    float contrib = 0.0f;
    for (int r = c.bg * rpb + warp; r < rend; r += 8) {
        const float* row = c.W + (size_t)r * c.N;
        float a0 = 0.f, a1 = 0.f, a2 = 0.f, a3 = 0.f;
        for (int j = lane; j < c.N; j += 128) {
            a0 += row[j] * c.ybuf[j];
            a1 += row[j + 32] * c.ybuf[j + 32];
            a2 += row[j + 64] * c.ybuf[j + 64];
            a3 += row[j + 96] * c.ybuf[j + 96];
        }
        float a = (a0 + a1) + (a2 + a3);
        for (int o = 16; o; o >>= 1) a += __shfl_down_sync(0xffffffffu, a, o);
        if (lane == 0) contrib += (su * c.ubuf[r]) * (sv * a);
    }
    __shared__ float wsq[8];
    if (lane == 0) wsq[warp] = contrib;
    __syncthreads();
    if (threadIdx.x == 0) {
        float p = 0.0f;
        for (int w = 0; w < 8; ++w) p += wsq[w];
        g_sigpart[c.m][c.bg] = p;
    }
}

__global__ void pi_finalize() {
    int m = threadIdx.x;
    if (m < 3) {
        int G = (m == 1) ? G_REC : ((m == 0) ? G_IN : G_OUT);
        float s = 0.0f;
        for (int g = 0; g < G; ++g) s += g_sigpart[m][g];
        g_inv_sigma[m] = 1.0f / s;
    }
}

// ---------------------------------------------------------------------------
// 3x-bf16 tensor-core GEMM (NT), mma.sync.m16n8k16.bf16 (legal on base sm_100):
//   C[m,n] = epi( (sum_k A[m,k]*B[n,k]) * inv_sigma + bias[n] [+ add] [tanh] )
// Split per element: hi = bf16(x), lo = bf16(x - hi); accumulate
// Ahi.Bhi + Ahi.Blo + Alo.Bhi in fp32 (dropped ll term ~2^-16 relative).
// Smem packs {hi(k),hi(k+1),lo(k),lo(k+1)} per 8B so one LDS.64 feeds both
// hi and lo fragments. Tile 128x128x32, 8 warps (2Mx4N), warp tile 64x32.
// ---------------------------------------------------------------------------
#define BM 128
#define BN 128
#define BKT 32
#define PSTRIDE 20   // uint2 per row: 16 k-pairs + 4 pad (160B: conflict-free phases)

// pack two fp32 -> bf16x2 (x0 in low half), residual pair likewise
__device__ __forceinline__ void split2(float x0, float x1, uint32_t& hi, uint32_t& lo) {
    uint32_t h;
    asm("cvt.rn.bf16x2.f32 %0, %1, %2;" : "=r"(h) : "f"(x1), "f"(x0));
    float h0 = __uint_as_float(h << 16);
    float h1 = __uint_as_float(h & 0xffff0000u);
    float r0 = x0 - h0, r1 = x1 - h1;
    uint32_t l;
    asm("cvt.rn.bf16x2.f32 %0, %1, %2;" : "=r"(l) : "f"(r1), "f"(r0));
    hi = h; lo = l;
}

__device__ __forceinline__ void mma16(float* c, uint32_t a0, uint32_t a1, uint32_t a2,
                                      uint32_t a3, uint32_t b0, uint32_t b1) {
    asm volatile(
        "mma.sync.aligned.m16n8k16.row.col.f32.bf16.bf16.f32 "
        "{%0,%1,%2,%3}, {%4,%5,%6,%7}, {%8,%9}, {%0,%1,%2,%3};"
        : "+f"(c[0]), "+f"(c[1]), "+f"(c[2]), "+f"(c[3])
        : "r"(a0), "r"(a1), "r"(a2), "r"(a3), "r"(b0), "r"(b1));
}

template <bool DO_TANH, bool HAS_ADD>
__global__ __launch_bounds__(256)
void gemm_bf16(const float* __restrict__ A, const float* __restrict__ B,
               const float* __restrict__ bias, const float* __restrict__ add,
               float* __restrict__ C, int M, int N, int K, int sidx) {
    __shared__ __align__(16) uint2 As[BM * PSTRIDE];   // 20 KB
    __shared__ __align__(16) uint2 Bs[BN * PSTRIDE];   // 20 KB

    int tid = threadIdx.x;
    int bm = blockIdx.y * BM, bn = blockIdx.x * BN;

    // fill mapping: 4 quanta, each thread covers (row, k4..k4+3)
    int rowq[4], k4q[4];
    bool bok[4];
#pragma unroll
    for (int q = 0; q < 4; ++q) {
        int idx = tid + q * 256;
        rowq[q] = idx >> 3;
        k4q[q] = (idx & 7) * 4;
        bok[q] = (bn + rowq[q]) < N;
    }

    int warp = tid >> 5, lane = tid & 31;
    int wm = (warp & 1) * 64;
    int wn = (warp >> 1) * 32;
    int g = lane >> 2;
    int t = lane & 3;

    float acc[4][4][4];
#pragma unroll
    for (int i = 0; i < 4; ++i)
#pragma unroll
        for (int j = 0; j < 4; ++j)
#pragma unroll
            for (int q = 0; q < 4; ++q) acc[i][j][q] = 0.0f;

    // prefetch tile 0
    float4 pa[4], pb[4];
#pragma unroll
    for (int q = 0; q < 4; ++q) {
        pa[q] = *(const float4*)(A + (size_t)(bm + rowq[q]) * K + k4q[q]);
        pb[q] = bok[q] ? *(const float4*)(B + (size_t)(bn + rowq[q]) * K + k4q[q])
                       : make_float4(0.f, 0.f, 0.f, 0.f);
    }

    int KT = K / BKT;
    for (int kt = 0; kt < KT; ++kt) {
        __syncthreads();   // previous tile fully consumed
#pragma unroll
        for (int q = 0; q < 4; ++q) {
            uint32_t h01, l01, h23, l23;
            split2(pa[q].x, pa[q].y, h01, l01);
            split2(pa[q].z, pa[q].w, h23, l23);
            *(uint4*)&As[rowq[q] * PSTRIDE + (k4q[q] >> 1)] = make_uint4(h01, l01, h23, l23);
            split2(pb[q].x, pb[q].y, h01, l01);
            split2(pb[q].z, pb[q].w, h23, l23);
            *(uint4*)&Bs[rowq[q] * PSTRIDE + (k4q[q] >> 1)] = make_uint4(h01, l01, h23, l23);
        }
        __syncthreads();

        // issue next tile's global loads; latency hidden by mma below
        if (kt + 1 < KT) {
            int off = (kt + 1) * BKT;
#pragma unroll
            for (int q = 0; q < 4; ++q) {
                pa[q] = *(const float4*)(A + (size_t)(bm + rowq[q]) * K + off + k4q[q]);
                if (bok[q]) pb[q] = *(const float4*)(B + (size_t)(bn + rowq[q]) * K + off + k4q[q]);
            }
        }

#pragma unroll
        for (int kp = 0; kp < 16; kp += 8) {   // two k16 sub-tiles (pair offsets 0, 8)
            uint2 Af[4][4];   // [mf][a0..a3], .x = hi pair, .y = lo pair
#pragma unroll
            for (int mf = 0; mf < 4; ++mf) {
                int rb = wm + mf * 16 + g;
                Af[mf][0] = As[rb * PSTRIDE + kp + t];
                Af[mf][1] = As[(rb + 8) * PSTRIDE + kp + t];
                Af[mf][2] = As[rb * PSTRIDE + kp + t + 4];
                Af[mf][3] = As[(rb + 8) * PSTRIDE + kp + t + 4];
            }
#pragma unroll
            for (int nf = 0; nf < 4; ++nf) {
                int cb = wn + nf * 8 + g;
                uint2 B0 = Bs[cb * PSTRIDE + kp + t];
                uint2 B1 = Bs[cb * PSTRIDE + kp + t + 4];
#pragma unroll
                for (int mf = 0; mf < 4; ++mf) {
                    mma16(acc[mf][nf], Af[mf][0].x, Af[mf][1].x, Af[mf][2].x, Af[mf][3].x,
                          B0.x, B1.x);                       // hi*hi
                    mma16(acc[mf][nf], Af[mf][0].x, Af[mf][1].x, Af[mf][2].x, Af[mf][3].x,
                          B0.y, B1.y);                       // hi*lo
                    mma16(acc[mf][nf], Af[mf][0].y, Af[mf][1].y, Af[mf][2].y, Af[mf][3].y,
                          B0.x, B1.x);                       // lo*hi
                }
            }
        }
    }

    // ---- epilogue (fragment c0,c1: row g cols 2t,2t+1; c2,c3: row g+8) ----
    float scale = g_inv_sigma[sidx];
    bool full = (bn + BN <= N);
#pragma unroll
    for (int mf = 0; mf < 4; ++mf) {
        int r0 = bm + wm + mf * 16 + g;
#pragma unroll
        for (int nf = 0; nf < 4; ++nf) {
            int c0 = bn + wn + nf * 8 + 2 * t;
            float* a = acc[mf][nf];
#pragma unroll
            for (int half = 0; half < 2; ++half) {
                int rr = r0 + half * 8;
                size_t base = (size_t)rr * N + c0;
                float v0 = a[half * 2 + 0];
                float v1 = a[half * 2 + 1];
                if (full) {
                    v0 = v0 * scale + bias[c0];
                    v1 = v1 * scale + bias[c0 + 1];
                    if (HAS_ADD) {
                        float2 ad = *(const float2*)(add + base);
                        v0 += ad.x; v1 += ad.y;
                    }
                    if (DO_TANH) { v0 = tanhf(v0); v1 = tanhf(v1); }
                    float2 o; o.x = v0; o.y = v1;
                    *(float2*)(C + base) = o;
                } else {
                    if (c0 < N) {
                        float w = v0 * scale + bias[c0];
                        if (HAS_ADD) w += add[base];
                        if (DO_TANH) w = tanhf(w);
                        C[base] = w;
                    }
                    if (c0 + 1 < N) {
                        float w = v1 * scale + bias[c0 + 1];
                        if (HAS_ADD) w += add[base + 1];
                        if (DO_TANH) w = tanhf(w);
                        C[base + 1] = w;
                    }
                }
            }
        }
    }
}

// Step 1 (h0 = 0): h = tanh(x_proj + b_rec)
__global__ void step1_kernel(const float* __restrict__ xp, const float* __restrict__ brec,
                             float* __restrict__ h) {
    size_t i = ((size_t)blockIdx.x * blockDim.x + threadIdx.x) * 4;
    float4 v = *(const float4*)(xp + i);
    int col = (int)(i & (HID - 1));
    v.x = tanhf(v.x + brec[col + 0]);
    v.y = tanhf(v.y + brec[col + 1]);
    v.z = tanhf(v.z + brec[col + 2]);
    v.w = tanhf(v.w + brec[col + 3]);
    *(float4*)(h + i) = v;
}

// ---------------------------------------------------------------------------
// Launch
// ---------------------------------------------------------------------------
extern "C" void kernel_launch(void* const* d_in, const int* in_sizes, int n_in,
                              void* d_out, int out_size) {
    (void)in_sizes; (void)n_in; (void)out_size;
    const float* x    = (const float*)d_in[0];
    const float* Win  = (const float*)d_in[1];
    const float* bin  = (const float*)d_in[2];
    const float* Wrec = (const float*)d_in[3];
    const float* brec = (const float*)d_in[4];
    const float* Wout = (const float*)d_in[5];
    const float* bout = (const float*)d_in[6];
    float* out = (float*)d_out;

    float *xproj, *h0, *h1;
    cudaGetSymbolAddress((void**)&xproj, g_xproj);
    cudaGetSymbolAddress((void**)&h0, g_h0);
    cudaGetSymbolAddress((void**)&h1, g_h1);

    // --- spectral norms (power iteration, fp32, exact reference sequence) ---
    pi_init<<<1, 256>>>();
    for (int it = 0; it < NPI; ++it) {
        pi_phaseY<<<NB_PI, 256>>>(Win, Wrec, Wout);
        pi_phaseZ<<<NB_PI, 256>>>(Win, Wrec, Wout);
    }
    pi_phaseY<<<NB_PI, 256>>>(Win, Wrec, Wout);   // final v = norm(W^T u)
    pi_sigma<<<NB_PI, 256>>>(Win, Wrec, Wout);    // sigma = u . (W v)
    pi_finalize<<<1, 32>>>();

    // --- x_proj = x @ Win^T / s_in + b_in ---
    gemm_bf16<false, false><<<dim3(HID / BN, BATCH / BM), 256>>>(
        x, Win, bin, nullptr, xproj, BATCH, HID, IN_DIM, 0);

    // --- step 1: h = tanh(x_proj + b_rec) ---
    step1_kernel<<<(BATCH * HID) / (256 * 4), 256>>>(xproj, brec, h0);

    // --- steps 2..30: h = tanh(x_proj + h @ Wrec^T / s_rec + b_rec) ---
    float* hin = h0;
    float* hout = h1;
    for (int s = 1; s < STEPS; ++s) {
        gemm_bf16<true, true><<<dim3(HID / BN, BATCH / BM), 256>>>(
            hin, Wrec, brec, xproj, hout, BATCH, HID, HID, 1);
        float* t = hin; hin = hout; hout = t;
    }

    // --- out = h @ Wout^T / s_out + b_out ---
    gemm_bf16<false, false><<<dim3((OUT_DIM + BN - 1) / BN, BATCH / BM), 256>>>(
        hin, Wout, bout, nullptr, out, BATCH, OUT_DIM, HID, 2);
}